// round 2
// baseline (speedup 1.0000x reference)
#include <cuda_runtime.h>
#include <math_constants.h>

#define N_PTS 16384
#define M_CTR 4096
#define K_NBR 32
#define F_IN  64
#define R2    0.25f

// output layout (float32, concatenated flatten of the reference tuple):
//   out      [M,128] at 0
//   pos[idx] [M,3]   at POS_OFF
//   batch[idx] [M]   at BATCH_OFF (all zeros -> handled by memset)
#define POS_OFF   (M_CTR * 128)
#define BATCH_OFF (POS_OFF + M_CTR * 3)

// ---------------- device globals (scratch; no allocations allowed) ---------
__device__ int  g_nedges;
__device__ int2 g_edges[M_CTR * K_NBR];

__global__ void init_kernel() { g_nedges = 0; }

// ---------------- Kernel 1: farthest point sampling (single block) ---------
// pos staged in dynamic smem (3*16384 floats = 192KB), dmin in registers
// (16 points per thread, 1024 threads). Exact argmax with first-occurrence
// (smallest index) tie-break, matching jnp.argmax.
#define FPS_SMEM_FLOATS (3 * N_PTS + 32 + 40)
#define FPS_SMEM_BYTES  (FPS_SMEM_FLOATS * 4)

__global__ __launch_bounds__(1024, 1) void fps_kernel(
    const float* __restrict__ pos, float* __restrict__ pos_out)
{
    extern __shared__ float sm[];
    float* sx = sm;
    float* sy = sm + N_PTS;
    float* sz = sm + 2 * N_PTS;
    float* rv = sm + 3 * N_PTS;        // 32 floats
    int*   ri = (int*)(rv + 32);       // 33 ints (32 partials + broadcast)

    const int tid  = threadIdx.x;
    const int lane = tid & 31;
    const int warp = tid >> 5;

    for (int i = tid; i < N_PTS; i += 1024) {
        sx[i] = pos[3 * i + 0];
        sy[i] = pos[3 * i + 1];
        sz[i] = pos[3 * i + 2];
    }
    __syncthreads();

    float bx = sx[0], by = sy[0], bz = sz[0];
    if (tid == 0) { pos_out[0] = bx; pos_out[1] = by; pos_out[2] = bz; }

    float dmin[16];
#pragma unroll
    for (int i = 0; i < 16; i++) dmin[i] = CUDART_INF_F;
    const int base = tid * 16;

    for (int t = 1; t < M_CTR; t++) {
        float vmax = -1.0f; int vidx = 0;
#pragma unroll
        for (int i = 0; i < 16; i++) {
            // plain mul/add (no fma contraction) to match reference rounding
            float dx = __fadd_rn(sx[base + i], -bx);
            float dy = __fadd_rn(sy[base + i], -by);
            float dz = __fadd_rn(sz[base + i], -bz);
            float d  = __fadd_rn(__fadd_rn(__fmul_rn(dx, dx), __fmul_rn(dy, dy)),
                                 __fmul_rn(dz, dz));
            float dm = fminf(dmin[i], d);
            dmin[i] = dm;
            if (dm > vmax) { vmax = dm; vidx = base + i; }  // first-max kept
        }
        // warp reduce (value desc, index asc tie-break)
#pragma unroll
        for (int off = 16; off > 0; off >>= 1) {
            float ov = __shfl_down_sync(0xffffffffu, vmax, off);
            int   oi = __shfl_down_sync(0xffffffffu, vidx, off);
            if (ov > vmax || (ov == vmax && oi < vidx)) { vmax = ov; vidx = oi; }
        }
        if (lane == 0) { rv[warp] = vmax; ri[warp] = vidx; }
        __syncthreads();
        if (warp == 0) {
            vmax = rv[lane]; vidx = ri[lane];
#pragma unroll
            for (int off = 16; off > 0; off >>= 1) {
                float ov = __shfl_down_sync(0xffffffffu, vmax, off);
                int   oi = __shfl_down_sync(0xffffffffu, vidx, off);
                if (ov > vmax || (ov == vmax && oi < vidx)) { vmax = ov; vidx = oi; }
            }
            if (lane == 0) ri[32] = vidx;
        }
        __syncthreads();
        int nxt = ri[32];
        bx = sx[nxt]; by = sy[nxt]; bz = sz[nxt];
        if (tid == 0) {
            pos_out[3 * t + 0] = bx;
            pos_out[3 * t + 1] = by;
            pos_out[3 * t + 2] = bz;
        }
    }
}

// ---------------- Kernel 2: ball query (one warp per center) ---------------
// Collect all points with d2 <= R2 (cap 128; exact nearest-32 rank-select if
// count > 32). Compacted into the global edge list.
__global__ __launch_bounds__(256) void nbr_kernel(
    const float* __restrict__ pos, const float* __restrict__ centers)
{
    __shared__ float s_d[8][128];
    __shared__ int   s_i[8][128];

    const int gw   = (blockIdx.x * 256 + threadIdx.x) >> 5;
    if (gw >= M_CTR) return;
    const int lane = threadIdx.x & 31;
    const int wl   = threadIdx.x >> 5;

    const float cx = centers[3 * gw + 0];
    const float cy = centers[3 * gw + 1];
    const float cz = centers[3 * gw + 2];

    int cnt = 0;
    for (int j = lane; j < N_PTS; j += 32) {
        float dx = __fadd_rn(cx, -pos[3 * j + 0]);
        float dy = __fadd_rn(cy, -pos[3 * j + 1]);
        float dz = __fadd_rn(cz, -pos[3 * j + 2]);
        float d2 = __fadd_rn(__fadd_rn(__fmul_rn(dx, dx), __fmul_rn(dy, dy)),
                             __fmul_rn(dz, dz));
        bool in = (d2 <= R2);
        unsigned mk = __ballot_sync(0xffffffffu, in);
        if (in) {
            int p = cnt + __popc(mk & ((1u << lane) - 1u));
            if (p < 128) { s_d[wl][p] = d2; s_i[wl][p] = j; }
        }
        cnt += __popc(mk);
    }
    if (cnt > 128) cnt = 128;
    __syncwarp();

    int keep = cnt < K_NBR ? cnt : K_NBR;
    int basee = 0;
    if (lane == 0) basee = atomicAdd(&g_nedges, keep);
    basee = __shfl_sync(0xffffffffu, basee, 0);

    if (cnt <= K_NBR) {
        if (lane < cnt) g_edges[basee + lane] = make_int2(gw, s_i[wl][lane]);
    } else {
        // exact rank selection: keep the 32 smallest d2 (index tie-break)
        for (int it = lane; it < cnt; it += 32) {
            float dv = s_d[wl][it]; int iv = s_i[wl][it];
            int r = 0;
            for (int o = 0; o < cnt; o++) {
                float od = s_d[wl][o]; int oi = s_i[wl][o];
                if (od < dv || (od == dv && oi < iv)) r++;
            }
            if (r < K_NBR) g_edges[basee + r] = make_int2(gw, iv);
        }
    }
}

// ---------------- Kernel 3: per-edge MLP + max aggregation -----------------
// One thread per edge; weights broadcast from smem; activations that need
// dynamic indexing live in local memory, accumulators in registers.
#define SW_W1 0
#define SW_W2 (67 * 64)
#define SW_W3 (SW_W2 + 64 * 64)
#define SW_B1 (SW_W3 + 64 * 128)
#define SW_B2 (SW_B1 + 64)
#define SW_B3 (SW_B2 + 64)
#define SW_TOT (SW_B3 + 128)

__global__ __launch_bounds__(128) void mlp_kernel(
    const float* __restrict__ features, const float* __restrict__ pos,
    const float* __restrict__ centers,
    const float* __restrict__ W1, const float* __restrict__ b1,
    const float* __restrict__ W2, const float* __restrict__ b2,
    const float* __restrict__ W3, const float* __restrict__ b3,
    float* __restrict__ out)
{
    extern __shared__ float sw[];
    const int tid = threadIdx.x;
    for (int i = tid; i < 67 * 64;  i += 128) sw[SW_W1 + i] = W1[i];
    for (int i = tid; i < 64 * 64;  i += 128) sw[SW_W2 + i] = W2[i];
    for (int i = tid; i < 64 * 128; i += 128) sw[SW_W3 + i] = W3[i];
    if (tid < 64)  { sw[SW_B1 + tid] = b1[tid]; sw[SW_B2 + tid] = b2[tid]; }
    if (tid < 128) { sw[SW_B3 + tid] = b3[tid]; }
    __syncthreads();

    const int n = g_nedges;
    const int stride = gridDim.x * blockDim.x;
    for (int e = blockIdx.x * blockDim.x + tid; e < n; e += stride) {
        int2 ed = g_edges[e];
        const int m = ed.x, j = ed.y;

        float xin[68];  // dynamic-indexed -> local memory
        {
            const float4* fr = reinterpret_cast<const float4*>(features + (size_t)j * F_IN);
            float4* x4 = reinterpret_cast<float4*>(xin);
#pragma unroll
            for (int q = 0; q < 16; q++) x4[q] = fr[q];
        }
        xin[64] = pos[3 * j + 0] - centers[3 * m + 0];
        xin[65] = pos[3 * j + 1] - centers[3 * m + 1];
        xin[66] = pos[3 * j + 2] - centers[3 * m + 2];
        xin[67] = 0.f;

        // ---- layer 1: 67 -> 64 ----
        float h[64];
#pragma unroll
        for (int o = 0; o < 64; o++) h[o] = sw[SW_B1 + o];
        for (int i = 0; i < 67; i++) {
            float x = xin[i];
            const float4* wr = reinterpret_cast<const float4*>(&sw[SW_W1 + i * 64]);
#pragma unroll
            for (int o4 = 0; o4 < 16; o4++) {
                float4 w = wr[o4];
                h[o4 * 4 + 0] += x * w.x; h[o4 * 4 + 1] += x * w.y;
                h[o4 * 4 + 2] += x * w.z; h[o4 * 4 + 3] += x * w.w;
            }
        }
        float l1[64];  // local
#pragma unroll
        for (int o = 0; o < 64; o++) l1[o] = fmaxf(h[o], 0.f);

        // ---- layer 2: 64 -> 64 ----
#pragma unroll
        for (int o = 0; o < 64; o++) h[o] = sw[SW_B2 + o];
        for (int i = 0; i < 64; i++) {
            float x = l1[i];
            const float4* wr = reinterpret_cast<const float4*>(&sw[SW_W2 + i * 64]);
#pragma unroll
            for (int o4 = 0; o4 < 16; o4++) {
                float4 w = wr[o4];
                h[o4 * 4 + 0] += x * w.x; h[o4 * 4 + 1] += x * w.y;
                h[o4 * 4 + 2] += x * w.z; h[o4 * 4 + 3] += x * w.w;
            }
        }
        float l2[64];  // local
#pragma unroll
        for (int o = 0; o < 64; o++) l2[o] = fmaxf(h[o], 0.f);

        // ---- layer 3: 64 -> 128 ----
        float g[128];
#pragma unroll
        for (int o = 0; o < 128; o++) g[o] = sw[SW_B3 + o];
        for (int i = 0; i < 64; i++) {
            float x = l2[i];
            const float4* wr = reinterpret_cast<const float4*>(&sw[SW_W3 + i * 128]);
#pragma unroll
            for (int o4 = 0; o4 < 32; o4++) {
                float4 w = wr[o4];
                g[o4 * 4 + 0] += x * w.x; g[o4 * 4 + 1] += x * w.y;
                g[o4 * 4 + 2] += x * w.z; g[o4 * 4 + 3] += x * w.w;
            }
        }

        // ---- max aggregation (all values >= 0 after relu; buffer zeroed) --
        int* om = (int*)(out + (size_t)m * 128);
#pragma unroll
        for (int o = 0; o < 128; o++) {
            atomicMax(om + o, __float_as_int(fmaxf(g[o], 0.f)));
        }
    }
}

// ---------------- launch ---------------------------------------------------
extern "C" void kernel_launch(void* const* d_in, const int* in_sizes, int n_in,
                              void* d_out, int out_size)
{
    const float* features = (const float*)d_in[0];
    const float* pos      = (const float*)d_in[1];
    // d_in[2] = batch (all zeros; output handled by memset)
    const float* W1 = (const float*)d_in[3];
    const float* b1 = (const float*)d_in[4];
    const float* W2 = (const float*)d_in[5];
    const float* b2 = (const float*)d_in[6];
    const float* W3 = (const float*)d_in[7];
    const float* b3 = (const float*)d_in[8];
    float* out = (float*)d_out;

    cudaFuncSetAttribute(fps_kernel, cudaFuncAttributeMaxDynamicSharedMemorySize,
                         FPS_SMEM_BYTES);
    cudaFuncSetAttribute(mlp_kernel, cudaFuncAttributeMaxDynamicSharedMemorySize,
                         SW_TOT * 4);

    // zero everything: out gets max'd (>=0), batch stays 0
    cudaMemsetAsync(d_out, 0, (size_t)out_size * sizeof(float));
    init_kernel<<<1, 1>>>();
    fps_kernel<<<1, 1024, FPS_SMEM_BYTES>>>(pos, out + POS_OFF);
    nbr_kernel<<<M_CTR / 8, 256>>>(pos, out + POS_OFF);
    mlp_kernel<<<512, 128, SW_TOT * 4>>>(features, pos, out + POS_OFF,
                                         W1, b1, W2, b2, W3, b3, out);
}

// round 3
// speedup vs baseline: 3.5082x; 3.5082x over previous
#include <cuda_runtime.h>
#include <math_constants.h>

#define N_PTS 16384
#define M_CTR 4096
#define K_NBR 32
#define F_IN  64
#define R2    0.25f
#define NCELL 512           // 8x8x8 morton cells

// output layout (float32, concatenated flatten of the reference tuple):
//   out      [M,128] at 0
//   pos[idx] [M,3]   at POS_OFF
//   batch[idx] [M]   at BATCH_OFF (zeros via memset)
#define POS_OFF   (M_CTR * 128)

// ---------------- device globals (scratch; no allocations allowed) ---------
__device__ int   g_nedges;
__device__ int2  g_edges[M_CTR * K_NBR];
__device__ int   g_cnt[NCELL];
__device__ int   g_start[NCELL];
__device__ int   g_fill[NCELL];
__device__ float g_sx[N_PTS], g_sy[N_PTS], g_sz[N_PTS];
__device__ int   g_oi[N_PTS];

__device__ __forceinline__ int spread3(int v) {
    return (v & 1) | ((v & 2) << 2) | ((v & 4) << 4);
}
__device__ __forceinline__ int cell_of(float x, float y, float z) {
    int cx = min(7, max(0, (int)(x * 0.8f)));
    int cy = min(7, max(0, (int)(y * 0.8f)));
    int cz = min(7, max(0, (int)(z * 0.8f)));
    return spread3(cx) | (spread3(cy) << 1) | (spread3(cz) << 2);
}

__global__ void init_kernel() {
    int t = threadIdx.x;
    if (t == 0) g_nedges = 0;
    if (t < NCELL) { g_cnt[t] = 0; g_fill[t] = 0; }
}

__global__ void cellcount_kernel(const float* __restrict__ pos) {
    int i = blockIdx.x * blockDim.x + threadIdx.x;
    if (i >= N_PTS) return;
    atomicAdd(&g_cnt[cell_of(pos[3*i], pos[3*i+1], pos[3*i+2])], 1);
}

__global__ void scan_kernel() {
    __shared__ int s[NCELL];
    int t = threadIdx.x;
    int my = g_cnt[t];
    s[t] = my;
    __syncthreads();
    for (int off = 1; off < NCELL; off <<= 1) {
        int v = (t >= off) ? s[t - off] : 0;
        __syncthreads();
        s[t] += v;
        __syncthreads();
    }
    g_start[t] = s[t] - my;   // exclusive
}

__global__ void scatter_kernel(const float* __restrict__ pos) {
    int i = blockIdx.x * blockDim.x + threadIdx.x;
    if (i >= N_PTS) return;
    float x = pos[3*i], y = pos[3*i+1], z = pos[3*i+2];
    int c = cell_of(x, y, z);
    int slot = g_start[c] + atomicAdd(&g_fill[c], 1);
    g_sx[slot] = x; g_sy[slot] = y; g_sz[slot] = z; g_oi[slot] = i;
}

// ---------------- Kernel: FPS, single block, 1024 thr, 16 pts/thread -------
// Morton-sorted points; warp w owns slots [w*512, w*512+512), slot layout
// w*512 + i*32 + lane  -> conflict-free LDS. Per-warp bbox skip is exact:
// omitting fminf(dmin, d) when d >= dmin leaves dmin bitwise unchanged.
#define FPS_SMEM_BYTES (3 * N_PTS * 4)

__global__ __launch_bounds__(1024, 1) void fps_kernel(
    const float* __restrict__ pos, float* __restrict__ pos_out)
{
    extern __shared__ float sm[];
    float* sx = sm;
    float* sy = sm + N_PTS;
    float* sz = sm + 2 * N_PTS;
    __shared__ float rv[32];
    __shared__ int   roi[32];
    __shared__ int   rs[32];
    __shared__ int   bslot;

    const int tid  = threadIdx.x;
    const int lane = tid & 31;
    const int warp = tid >> 5;
    const unsigned FULL = 0xffffffffu;

    for (int i = tid; i < N_PTS; i += 1024) {
        sx[i] = g_sx[i]; sy[i] = g_sy[i]; sz[i] = g_sz[i];
    }
    __syncthreads();

    const int chunk = warp * 512;
    float dmin[16];
    int   oi[16];
    float mnx = CUDART_INF_F, mny = CUDART_INF_F, mnz = CUDART_INF_F;
    float mxx = -CUDART_INF_F, mxy = -CUDART_INF_F, mxz = -CUDART_INF_F;
#pragma unroll
    for (int i = 0; i < 16; i++) {
        int slot = chunk + i * 32 + lane;
        dmin[i] = CUDART_INF_F;
        oi[i]   = g_oi[slot];
        float x = sx[slot], y = sy[slot], z = sz[slot];
        mnx = fminf(mnx, x); mxx = fmaxf(mxx, x);
        mny = fminf(mny, y); mxy = fmaxf(mxy, y);
        mnz = fminf(mnz, z); mxz = fmaxf(mxz, z);
    }
    // warp-wide bbox (all lanes converge)
#pragma unroll
    for (int off = 16; off > 0; off >>= 1) {
        mnx = fminf(mnx, __shfl_xor_sync(FULL, mnx, off));
        mxx = fmaxf(mxx, __shfl_xor_sync(FULL, mxx, off));
        mny = fminf(mny, __shfl_xor_sync(FULL, mny, off));
        mxy = fmaxf(mxy, __shfl_xor_sync(FULL, mxy, off));
        mnz = fminf(mnz, __shfl_xor_sync(FULL, mnz, off));
        mxz = fmaxf(mxz, __shfl_xor_sync(FULL, mxz, off));
    }

    // first sample = original point 0
    float bx = pos[0], by = pos[1], bz = pos[2];
    if (tid == 0) { pos_out[0] = bx; pos_out[1] = by; pos_out[2] = bz; }

    float cval = CUDART_INF_F;   // warp's cached candidate value (= warp Bmax)

    for (int t = 1; t < M_CTR; t++) {
        // exact skip test: lb(sample,bbox) with small margin for lb rounding
        float ddx = fmaxf(fmaxf(mnx - bx, bx - mxx), 0.f);
        float ddy = fmaxf(fmaxf(mny - by, by - mxy), 0.f);
        float ddz = fmaxf(fmaxf(mnz - bz, bz - mxz), 0.f);
        float lb  = ddx * ddx + ddy * ddy + ddz * ddz;
        if (!(lb > cval * 1.00001f)) {
            float vmax = -1.0f; int voi = 0x7fffffff; int vslot = 0;
#pragma unroll
            for (int i = 0; i < 16; i++) {
                int slot = chunk + i * 32 + lane;
                // plain mul/add (no fma contraction) to match reference bits
                float dx = __fadd_rn(sx[slot], -bx);
                float dy = __fadd_rn(sy[slot], -by);
                float dz = __fadd_rn(sz[slot], -bz);
                float d  = __fadd_rn(__fadd_rn(__fmul_rn(dx, dx), __fmul_rn(dy, dy)),
                                     __fmul_rn(dz, dz));
                float dm = fminf(dmin[i], d);
                dmin[i] = dm;
                bool better = (dm > vmax) || (dm == vmax && oi[i] < voi);
                if (better) { vmax = dm; voi = oi[i]; vslot = slot; }
            }
            // warp reduce (value desc, orig-idx asc), all lanes converge
#pragma unroll
            for (int off = 16; off > 0; off >>= 1) {
                float ov = __shfl_xor_sync(FULL, vmax, off);
                int   oo = __shfl_xor_sync(FULL, voi,  off);
                int   os = __shfl_xor_sync(FULL, vslot, off);
                if (ov > vmax || (ov == vmax && oo < voi)) {
                    vmax = ov; voi = oo; vslot = os;
                }
            }
            cval = vmax;
            if (lane == 0) { rv[warp] = vmax; roi[warp] = voi; rs[warp] = vslot; }
        }
        __syncthreads();
        if (warp == 0) {
            float vmax = rv[lane]; int voi = roi[lane]; int vslot = rs[lane];
#pragma unroll
            for (int off = 16; off > 0; off >>= 1) {
                float ov = __shfl_xor_sync(FULL, vmax, off);
                int   oo = __shfl_xor_sync(FULL, voi,  off);
                int   os = __shfl_xor_sync(FULL, vslot, off);
                if (ov > vmax || (ov == vmax && oo < voi)) {
                    vmax = ov; voi = oo; vslot = os;
                }
            }
            if (lane == 0) bslot = vslot;
        }
        __syncthreads();
        int s = bslot;
        bx = sx[s]; by = sy[s]; bz = sz[s];
        if (tid == 0) {
            pos_out[3 * t + 0] = bx;
            pos_out[3 * t + 1] = by;
            pos_out[3 * t + 2] = bz;
        }
    }
}

// ---------------- Kernel: ball query (one warp per center) -----------------
__global__ __launch_bounds__(256) void nbr_kernel(
    const float* __restrict__ pos, const float* __restrict__ centers)
{
    __shared__ float s_d[8][128];
    __shared__ int   s_i[8][128];

    const int gw   = (blockIdx.x * 256 + threadIdx.x) >> 5;
    if (gw >= M_CTR) return;
    const int lane = threadIdx.x & 31;
    const int wl   = threadIdx.x >> 5;

    const float cx = centers[3 * gw + 0];
    const float cy = centers[3 * gw + 1];
    const float cz = centers[3 * gw + 2];

    int cnt = 0;
    for (int j = lane; j < N_PTS; j += 32) {
        float dx = __fadd_rn(cx, -pos[3 * j + 0]);
        float dy = __fadd_rn(cy, -pos[3 * j + 1]);
        float dz = __fadd_rn(cz, -pos[3 * j + 2]);
        float d2 = __fadd_rn(__fadd_rn(__fmul_rn(dx, dx), __fmul_rn(dy, dy)),
                             __fmul_rn(dz, dz));
        bool in = (d2 <= R2);
        unsigned mk = __ballot_sync(0xffffffffu, in);
        if (in) {
            int p = cnt + __popc(mk & ((1u << lane) - 1u));
            if (p < 128) { s_d[wl][p] = d2; s_i[wl][p] = j; }
        }
        cnt += __popc(mk);
    }
    if (cnt > 128) cnt = 128;
    __syncwarp();

    int keep = cnt < K_NBR ? cnt : K_NBR;
    int basee = 0;
    if (lane == 0) basee = atomicAdd(&g_nedges, keep);
    basee = __shfl_sync(0xffffffffu, basee, 0);

    if (cnt <= K_NBR) {
        if (lane < cnt) g_edges[basee + lane] = make_int2(gw, s_i[wl][lane]);
    } else {
        for (int it = lane; it < cnt; it += 32) {
            float dv = s_d[wl][it]; int iv = s_i[wl][it];
            int r = 0;
            for (int o = 0; o < cnt; o++) {
                float od = s_d[wl][o]; int oo = s_i[wl][o];
                if (od < dv || (od == dv && oo < iv)) r++;
            }
            if (r < K_NBR) g_edges[basee + r] = make_int2(gw, iv);
        }
    }
}

// ---------------- Kernel: per-edge MLP + max aggregation -------------------
#define SW_W1 0
#define SW_W2 (67 * 64)
#define SW_W3 (SW_W2 + 64 * 64)
#define SW_B1 (SW_W3 + 64 * 128)
#define SW_B2 (SW_B1 + 64)
#define SW_B3 (SW_B2 + 64)
#define SW_TOT (SW_B3 + 128)

__global__ __launch_bounds__(128) void mlp_kernel(
    const float* __restrict__ features, const float* __restrict__ pos,
    const float* __restrict__ centers,
    const float* __restrict__ W1, const float* __restrict__ b1,
    const float* __restrict__ W2, const float* __restrict__ b2,
    const float* __restrict__ W3, const float* __restrict__ b3,
    float* __restrict__ out)
{
    extern __shared__ float sw[];
    const int tid = threadIdx.x;
    for (int i = tid; i < 67 * 64;  i += 128) sw[SW_W1 + i] = W1[i];
    for (int i = tid; i < 64 * 64;  i += 128) sw[SW_W2 + i] = W2[i];
    for (int i = tid; i < 64 * 128; i += 128) sw[SW_W3 + i] = W3[i];
    if (tid < 64)  { sw[SW_B1 + tid] = b1[tid]; sw[SW_B2 + tid] = b2[tid]; }
    if (tid < 128) { sw[SW_B3 + tid] = b3[tid]; }
    __syncthreads();

    const int n = g_nedges;
    const int stride = gridDim.x * blockDim.x;
    for (int e = blockIdx.x * blockDim.x + tid; e < n; e += stride) {
        int2 ed = g_edges[e];
        const int m = ed.x, j = ed.y;

        float xin[68];
        {
            const float4* fr = reinterpret_cast<const float4*>(features + (size_t)j * F_IN);
            float4* x4 = reinterpret_cast<float4*>(xin);
#pragma unroll
            for (int q = 0; q < 16; q++) x4[q] = fr[q];
        }
        xin[64] = pos[3 * j + 0] - centers[3 * m + 0];
        xin[65] = pos[3 * j + 1] - centers[3 * m + 1];
        xin[66] = pos[3 * j + 2] - centers[3 * m + 2];
        xin[67] = 0.f;

        float h[64];
#pragma unroll
        for (int o = 0; o < 64; o++) h[o] = sw[SW_B1 + o];
        for (int i = 0; i < 67; i++) {
            float x = xin[i];
            const float4* wr = reinterpret_cast<const float4*>(&sw[SW_W1 + i * 64]);
#pragma unroll
            for (int o4 = 0; o4 < 16; o4++) {
                float4 w = wr[o4];
                h[o4 * 4 + 0] += x * w.x; h[o4 * 4 + 1] += x * w.y;
                h[o4 * 4 + 2] += x * w.z; h[o4 * 4 + 3] += x * w.w;
            }
        }
        float l1[64];
#pragma unroll
        for (int o = 0; o < 64; o++) l1[o] = fmaxf(h[o], 0.f);

#pragma unroll
        for (int o = 0; o < 64; o++) h[o] = sw[SW_B2 + o];
        for (int i = 0; i < 64; i++) {
            float x = l1[i];
            const float4* wr = reinterpret_cast<const float4*>(&sw[SW_W2 + i * 64]);
#pragma unroll
            for (int o4 = 0; o4 < 16; o4++) {
                float4 w = wr[o4];
                h[o4 * 4 + 0] += x * w.x; h[o4 * 4 + 1] += x * w.y;
                h[o4 * 4 + 2] += x * w.z; h[o4 * 4 + 3] += x * w.w;
            }
        }
        float l2[64];
#pragma unroll
        for (int o = 0; o < 64; o++) l2[o] = fmaxf(h[o], 0.f);

        float g[128];
#pragma unroll
        for (int o = 0; o < 128; o++) g[o] = sw[SW_B3 + o];
        for (int i = 0; i < 64; i++) {
            float x = l2[i];
            const float4* wr = reinterpret_cast<const float4*>(&sw[SW_W3 + i * 128]);
#pragma unroll
            for (int o4 = 0; o4 < 32; o4++) {
                float4 w = wr[o4];
                g[o4 * 4 + 0] += x * w.x; g[o4 * 4 + 1] += x * w.y;
                g[o4 * 4 + 2] += x * w.z; g[o4 * 4 + 3] += x * w.w;
            }
        }

        int* om = (int*)(out + (size_t)m * 128);
#pragma unroll
        for (int o = 0; o < 128; o++) {
            atomicMax(om + o, __float_as_int(fmaxf(g[o], 0.f)));
        }
    }
}

// ---------------- launch ---------------------------------------------------
extern "C" void kernel_launch(void* const* d_in, const int* in_sizes, int n_in,
                              void* d_out, int out_size)
{
    const float* features = (const float*)d_in[0];
    const float* pos      = (const float*)d_in[1];
    const float* W1 = (const float*)d_in[3];
    const float* b1 = (const float*)d_in[4];
    const float* W2 = (const float*)d_in[5];
    const float* b2 = (const float*)d_in[6];
    const float* W3 = (const float*)d_in[7];
    const float* b3 = (const float*)d_in[8];
    float* out = (float*)d_out;

    cudaFuncSetAttribute(fps_kernel, cudaFuncAttributeMaxDynamicSharedMemorySize,
                         FPS_SMEM_BYTES);
    cudaFuncSetAttribute(mlp_kernel, cudaFuncAttributeMaxDynamicSharedMemorySize,
                         SW_TOT * 4);

    cudaMemsetAsync(d_out, 0, (size_t)out_size * sizeof(float));
    init_kernel<<<1, NCELL>>>();
    cellcount_kernel<<<N_PTS / 256, 256>>>(pos);
    scan_kernel<<<1, NCELL>>>();
    scatter_kernel<<<N_PTS / 256, 256>>>(pos);
    fps_kernel<<<1, 1024, FPS_SMEM_BYTES>>>(pos, out + POS_OFF);
    nbr_kernel<<<M_CTR / 8, 256>>>(pos, out + POS_OFF);
    mlp_kernel<<<512, 128, SW_TOT * 4>>>(features, pos, out + POS_OFF,
                                         W1, b1, W2, b2, W3, b3, out);
}

// round 4
// speedup vs baseline: 3.5098x; 1.0005x over previous
#include <cuda_runtime.h>
#include <math_constants.h>

#define N_PTS 16384
#define M_CTR 4096
#define K_NBR 32
#define F_IN  64
#define R2    0.25f
#define NCELL 512           // 8x8x8 morton cells

// output layout (float32, concatenated flatten of the reference tuple):
//   out      [M,128] at 0
//   pos[idx] [M,3]   at POS_OFF
//   batch[idx] [M]   at BATCH_OFF (zeros via memset)
#define POS_OFF   (M_CTR * 128)

// ---------------- device globals (scratch; no allocations allowed) ---------
__device__ int   g_nedges;
__device__ int2  g_edges[M_CTR * K_NBR];
__device__ int   g_cnt[NCELL];
__device__ int   g_start[NCELL];
__device__ int   g_fill[NCELL];
__device__ float g_sx[N_PTS], g_sy[N_PTS], g_sz[N_PTS];
__device__ int   g_oi[N_PTS];

__device__ __forceinline__ int spread3(int v) {
    return (v & 1) | ((v & 2) << 2) | ((v & 4) << 4);
}
__device__ __forceinline__ int cell_of(float x, float y, float z) {
    int cx = min(7, max(0, (int)(x * 0.8f)));
    int cy = min(7, max(0, (int)(y * 0.8f)));
    int cz = min(7, max(0, (int)(z * 0.8f)));
    return spread3(cx) | (spread3(cy) << 1) | (spread3(cz) << 2);
}

__global__ void init_kernel() {
    int t = threadIdx.x;
    if (t == 0) g_nedges = 0;
    if (t < NCELL) { g_cnt[t] = 0; g_fill[t] = 0; }
}

__global__ void cellcount_kernel(const float* __restrict__ pos) {
    int i = blockIdx.x * blockDim.x + threadIdx.x;
    if (i >= N_PTS) return;
    atomicAdd(&g_cnt[cell_of(pos[3*i], pos[3*i+1], pos[3*i+2])], 1);
}

__global__ void scan_kernel() {
    __shared__ int s[NCELL];
    int t = threadIdx.x;
    int my = g_cnt[t];
    s[t] = my;
    __syncthreads();
    for (int off = 1; off < NCELL; off <<= 1) {
        int v = (t >= off) ? s[t - off] : 0;
        __syncthreads();
        s[t] += v;
        __syncthreads();
    }
    g_start[t] = s[t] - my;   // exclusive
}

__global__ void scatter_kernel(const float* __restrict__ pos) {
    int i = blockIdx.x * blockDim.x + threadIdx.x;
    if (i >= N_PTS) return;
    float x = pos[3*i], y = pos[3*i+1], z = pos[3*i+2];
    int c = cell_of(x, y, z);
    int slot = g_start[c] + atomicAdd(&g_fill[c], 1);
    g_sx[slot] = x; g_sy[slot] = y; g_sz[slot] = z; g_oi[slot] = i;
}

// ---------------- Kernel: FPS, single block, 1024 thr, 16 pts/thread -------
// Morton-sorted points; warp w owns slots [w*512, w*512+512), slot layout
// w*512 + i*32 + lane  -> conflict-free LDS. Per-warp bbox skip is exact:
// omitting fminf(dmin, d) when d >= dmin leaves dmin bitwise unchanged.
#define FPS_SMEM_BYTES (3 * N_PTS * 4)

__global__ __launch_bounds__(1024, 1) void fps_kernel(
    const float* __restrict__ pos, float* __restrict__ pos_out)
{
    extern __shared__ float sm[];
    float* sx = sm;
    float* sy = sm + N_PTS;
    float* sz = sm + 2 * N_PTS;
    __shared__ float rv[32];
    __shared__ int   roi[32];
    __shared__ int   rs[32];
    __shared__ int   bslot;

    const int tid  = threadIdx.x;
    const int lane = tid & 31;
    const int warp = tid >> 5;
    const unsigned FULL = 0xffffffffu;

    for (int i = tid; i < N_PTS; i += 1024) {
        sx[i] = g_sx[i]; sy[i] = g_sy[i]; sz[i] = g_sz[i];
    }
    __syncthreads();

    const int chunk = warp * 512;
    float dmin[16];
    int   oi[16];
    float mnx = CUDART_INF_F, mny = CUDART_INF_F, mnz = CUDART_INF_F;
    float mxx = -CUDART_INF_F, mxy = -CUDART_INF_F, mxz = -CUDART_INF_F;
#pragma unroll
    for (int i = 0; i < 16; i++) {
        int slot = chunk + i * 32 + lane;
        dmin[i] = CUDART_INF_F;
        oi[i]   = g_oi[slot];
        float x = sx[slot], y = sy[slot], z = sz[slot];
        mnx = fminf(mnx, x); mxx = fmaxf(mxx, x);
        mny = fminf(mny, y); mxy = fmaxf(mxy, y);
        mnz = fminf(mnz, z); mxz = fmaxf(mxz, z);
    }
    // warp-wide bbox (all lanes converge)
#pragma unroll
    for (int off = 16; off > 0; off >>= 1) {
        mnx = fminf(mnx, __shfl_xor_sync(FULL, mnx, off));
        mxx = fmaxf(mxx, __shfl_xor_sync(FULL, mxx, off));
        mny = fminf(mny, __shfl_xor_sync(FULL, mny, off));
        mxy = fmaxf(mxy, __shfl_xor_sync(FULL, mxy, off));
        mnz = fminf(mnz, __shfl_xor_sync(FULL, mnz, off));
        mxz = fmaxf(mxz, __shfl_xor_sync(FULL, mxz, off));
    }

    // first sample = original point 0
    float bx = pos[0], by = pos[1], bz = pos[2];
    if (tid == 0) { pos_out[0] = bx; pos_out[1] = by; pos_out[2] = bz; }

    float cval = CUDART_INF_F;   // warp's cached candidate value (= warp Bmax)

    for (int t = 1; t < M_CTR; t++) {
        // exact skip test: lb(sample,bbox) with small margin for lb rounding
        float ddx = fmaxf(fmaxf(mnx - bx, bx - mxx), 0.f);
        float ddy = fmaxf(fmaxf(mny - by, by - mxy), 0.f);
        float ddz = fmaxf(fmaxf(mnz - bz, bz - mxz), 0.f);
        float lb  = ddx * ddx + ddy * ddy + ddz * ddz;
        if (!(lb > cval * 1.00001f)) {
            float vmax = -1.0f; int voi = 0x7fffffff; int vslot = 0;
#pragma unroll
            for (int i = 0; i < 16; i++) {
                int slot = chunk + i * 32 + lane;
                // plain mul/add (no fma contraction) to match reference bits
                float dx = __fadd_rn(sx[slot], -bx);
                float dy = __fadd_rn(sy[slot], -by);
                float dz = __fadd_rn(sz[slot], -bz);
                float d  = __fadd_rn(__fadd_rn(__fmul_rn(dx, dx), __fmul_rn(dy, dy)),
                                     __fmul_rn(dz, dz));
                float dm = fminf(dmin[i], d);
                dmin[i] = dm;
                bool better = (dm > vmax) || (dm == vmax && oi[i] < voi);
                if (better) { vmax = dm; voi = oi[i]; vslot = slot; }
            }
            // warp reduce (value desc, orig-idx asc), all lanes converge
#pragma unroll
            for (int off = 16; off > 0; off >>= 1) {
                float ov = __shfl_xor_sync(FULL, vmax, off);
                int   oo = __shfl_xor_sync(FULL, voi,  off);
                int   os = __shfl_xor_sync(FULL, vslot, off);
                if (ov > vmax || (ov == vmax && oo < voi)) {
                    vmax = ov; voi = oo; vslot = os;
                }
            }
            cval = vmax;
            if (lane == 0) { rv[warp] = vmax; roi[warp] = voi; rs[warp] = vslot; }
        }
        __syncthreads();
        if (warp == 0) {
            float vmax = rv[lane]; int voi = roi[lane]; int vslot = rs[lane];
#pragma unroll
            for (int off = 16; off > 0; off >>= 1) {
                float ov = __shfl_xor_sync(FULL, vmax, off);
                int   oo = __shfl_xor_sync(FULL, voi,  off);
                int   os = __shfl_xor_sync(FULL, vslot, off);
                if (ov > vmax || (ov == vmax && oo < voi)) {
                    vmax = ov; voi = oo; vslot = os;
                }
            }
            if (lane == 0) bslot = vslot;
        }
        __syncthreads();
        int s = bslot;
        bx = sx[s]; by = sy[s]; bz = sz[s];
        if (tid == 0) {
            pos_out[3 * t + 0] = bx;
            pos_out[3 * t + 1] = by;
            pos_out[3 * t + 2] = bz;
        }
    }
}

// ---------------- Kernel: ball query (one warp per center) -----------------
__global__ __launch_bounds__(256) void nbr_kernel(
    const float* __restrict__ pos, const float* __restrict__ centers)
{
    __shared__ float s_d[8][128];
    __shared__ int   s_i[8][128];

    const int gw   = (blockIdx.x * 256 + threadIdx.x) >> 5;
    if (gw >= M_CTR) return;
    const int lane = threadIdx.x & 31;
    const int wl   = threadIdx.x >> 5;

    const float cx = centers[3 * gw + 0];
    const float cy = centers[3 * gw + 1];
    const float cz = centers[3 * gw + 2];

    int cnt = 0;
    for (int j = lane; j < N_PTS; j += 32) {
        float dx = __fadd_rn(cx, -pos[3 * j + 0]);
        float dy = __fadd_rn(cy, -pos[3 * j + 1]);
        float dz = __fadd_rn(cz, -pos[3 * j + 2]);
        float d2 = __fadd_rn(__fadd_rn(__fmul_rn(dx, dx), __fmul_rn(dy, dy)),
                             __fmul_rn(dz, dz));
        bool in = (d2 <= R2);
        unsigned mk = __ballot_sync(0xffffffffu, in);
        if (in) {
            int p = cnt + __popc(mk & ((1u << lane) - 1u));
            if (p < 128) { s_d[wl][p] = d2; s_i[wl][p] = j; }
        }
        cnt += __popc(mk);
    }
    if (cnt > 128) cnt = 128;
    __syncwarp();

    int keep = cnt < K_NBR ? cnt : K_NBR;
    int basee = 0;
    if (lane == 0) basee = atomicAdd(&g_nedges, keep);
    basee = __shfl_sync(0xffffffffu, basee, 0);

    if (cnt <= K_NBR) {
        if (lane < cnt) g_edges[basee + lane] = make_int2(gw, s_i[wl][lane]);
    } else {
        for (int it = lane; it < cnt; it += 32) {
            float dv = s_d[wl][it]; int iv = s_i[wl][it];
            int r = 0;
            for (int o = 0; o < cnt; o++) {
                float od = s_d[wl][o]; int oo = s_i[wl][o];
                if (od < dv || (od == dv && oo < iv)) r++;
            }
            if (r < K_NBR) g_edges[basee + r] = make_int2(gw, iv);
        }
    }
}

// ---------------- Kernel: per-edge MLP + max aggregation -------------------
#define SW_W1 0
#define SW_W2 (67 * 64)
#define SW_W3 (SW_W2 + 64 * 64)
#define SW_B1 (SW_W3 + 64 * 128)
#define SW_B2 (SW_B1 + 64)
#define SW_B3 (SW_B2 + 64)
#define SW_TOT (SW_B3 + 128)

__global__ __launch_bounds__(128) void mlp_kernel(
    const float* __restrict__ features, const float* __restrict__ pos,
    const float* __restrict__ centers,
    const float* __restrict__ W1, const float* __restrict__ b1,
    const float* __restrict__ W2, const float* __restrict__ b2,
    const float* __restrict__ W3, const float* __restrict__ b3,
    float* __restrict__ out)
{
    extern __shared__ float sw[];
    const int tid = threadIdx.x;
    for (int i = tid; i < 67 * 64;  i += 128) sw[SW_W1 + i] = W1[i];
    for (int i = tid; i < 64 * 64;  i += 128) sw[SW_W2 + i] = W2[i];
    for (int i = tid; i < 64 * 128; i += 128) sw[SW_W3 + i] = W3[i];
    if (tid < 64)  { sw[SW_B1 + tid] = b1[tid]; sw[SW_B2 + tid] = b2[tid]; }
    if (tid < 128) { sw[SW_B3 + tid] = b3[tid]; }
    __syncthreads();

    const int n = g_nedges;
    const int stride = gridDim.x * blockDim.x;
    for (int e = blockIdx.x * blockDim.x + tid; e < n; e += stride) {
        int2 ed = g_edges[e];
        const int m = ed.x, j = ed.y;

        float xin[68];
        {
            const float4* fr = reinterpret_cast<const float4*>(features + (size_t)j * F_IN);
            float4* x4 = reinterpret_cast<float4*>(xin);
#pragma unroll
            for (int q = 0; q < 16; q++) x4[q] = fr[q];
        }
        xin[64] = pos[3 * j + 0] - centers[3 * m + 0];
        xin[65] = pos[3 * j + 1] - centers[3 * m + 1];
        xin[66] = pos[3 * j + 2] - centers[3 * m + 2];
        xin[67] = 0.f;

        float h[64];
#pragma unroll
        for (int o = 0; o < 64; o++) h[o] = sw[SW_B1 + o];
        for (int i = 0; i < 67; i++) {
            float x = xin[i];
            const float4* wr = reinterpret_cast<const float4*>(&sw[SW_W1 + i * 64]);
#pragma unroll
            for (int o4 = 0; o4 < 16; o4++) {
                float4 w = wr[o4];
                h[o4 * 4 + 0] += x * w.x; h[o4 * 4 + 1] += x * w.y;
                h[o4 * 4 + 2] += x * w.z; h[o4 * 4 + 3] += x * w.w;
            }
        }
        float l1[64];
#pragma unroll
        for (int o = 0; o < 64; o++) l1[o] = fmaxf(h[o], 0.f);

#pragma unroll
        for (int o = 0; o < 64; o++) h[o] = sw[SW_B2 + o];
        for (int i = 0; i < 64; i++) {
            float x = l1[i];
            const float4* wr = reinterpret_cast<const float4*>(&sw[SW_W2 + i * 64]);
#pragma unroll
            for (int o4 = 0; o4 < 16; o4++) {
                float4 w = wr[o4];
                h[o4 * 4 + 0] += x * w.x; h[o4 * 4 + 1] += x * w.y;
                h[o4 * 4 + 2] += x * w.z; h[o4 * 4 + 3] += x * w.w;
            }
        }
        float l2[64];
#pragma unroll
        for (int o = 0; o < 64; o++) l2[o] = fmaxf(h[o], 0.f);

        float g[128];
#pragma unroll
        for (int o = 0; o < 128; o++) g[o] = sw[SW_B3 + o];
        for (int i = 0; i < 64; i++) {
            float x = l2[i];
            const float4* wr = reinterpret_cast<const float4*>(&sw[SW_W3 + i * 128]);
#pragma unroll
            for (int o4 = 0; o4 < 32; o4++) {
                float4 w = wr[o4];
                g[o4 * 4 + 0] += x * w.x; g[o4 * 4 + 1] += x * w.y;
                g[o4 * 4 + 2] += x * w.z; g[o4 * 4 + 3] += x * w.w;
            }
        }

        int* om = (int*)(out + (size_t)m * 128);
#pragma unroll
        for (int o = 0; o < 128; o++) {
            atomicMax(om + o, __float_as_int(fmaxf(g[o], 0.f)));
        }
    }
}

// ---------------- launch ---------------------------------------------------
extern "C" void kernel_launch(void* const* d_in, const int* in_sizes, int n_in,
                              void* d_out, int out_size)
{
    const float* features = (const float*)d_in[0];
    const float* pos      = (const float*)d_in[1];
    const float* W1 = (const float*)d_in[3];
    const float* b1 = (const float*)d_in[4];
    const float* W2 = (const float*)d_in[5];
    const float* b2 = (const float*)d_in[6];
    const float* W3 = (const float*)d_in[7];
    const float* b3 = (const float*)d_in[8];
    float* out = (float*)d_out;

    cudaFuncSetAttribute(fps_kernel, cudaFuncAttributeMaxDynamicSharedMemorySize,
                         FPS_SMEM_BYTES);
    cudaFuncSetAttribute(mlp_kernel, cudaFuncAttributeMaxDynamicSharedMemorySize,
                         SW_TOT * 4);

    cudaMemsetAsync(d_out, 0, (size_t)out_size * sizeof(float));
    init_kernel<<<1, NCELL>>>();
    cellcount_kernel<<<N_PTS / 256, 256>>>(pos);
    scan_kernel<<<1, NCELL>>>();
    scatter_kernel<<<N_PTS / 256, 256>>>(pos);
    fps_kernel<<<1, 1024, FPS_SMEM_BYTES>>>(pos, out + POS_OFF);
    nbr_kernel<<<M_CTR / 8, 256>>>(pos, out + POS_OFF);
    mlp_kernel<<<512, 128, SW_TOT * 4>>>(features, pos, out + POS_OFF,
                                         W1, b1, W2, b2, W3, b3, out);
}